// round 1
// baseline (speedup 1.0000x reference)
#include <cuda_runtime.h>
#include <math.h>

#define NPIX  16384   // 4*64*64
#define CDIM  128
#define NHEAD 4
#define DHEAD 32
#define KWIN  7

// Scratch (device globals: no allocations allowed)
__device__ float g_q[NPIX * CDIM];
__device__ float g_k[NPIX * CDIM];
__device__ float g_v[NPIX * CDIM];
__device__ float g_att[NPIX * CDIM];

// ---------------------------------------------------------------------------
// GEMM 1: qkv = x @ w_qkv + b_qkv ; split into q (scaled), k, v
// A: [16384, 128], B: [128, 384]. Tile 64x64, BK=64, 4x4 per thread.
// ---------------------------------------------------------------------------
__global__ __launch_bounds__(256) void qkv_gemm(
    const float* __restrict__ x,
    const float* __restrict__ w,       // [128, 384]
    const float* __restrict__ bias)    // [384]
{
    __shared__ float As[64 * 64];
    __shared__ float Bs[64 * 64];

    const int bm = blockIdx.x;
    const int bn = blockIdx.y;
    const int tid = threadIdx.x;
    const int tx = tid & 15;
    const int ty = tid >> 4;

    float acc[4][4] = {};

    for (int kt = 0; kt < 2; kt++) {
        // Load A tile 64x64 (row-major), float4 coalesced
        #pragma unroll
        for (int i = 0; i < 4; i++) {
            int idx = tid + i * 256;
            int r = idx >> 4;
            int c = (idx & 15) << 2;
            *(float4*)&As[r * 64 + c] =
                *(const float4*)&x[(size_t)(bm * 64 + r) * 128 + kt * 64 + c];
        }
        // Load B tile 64x64
        #pragma unroll
        for (int i = 0; i < 4; i++) {
            int idx = tid + i * 256;
            int r = idx >> 4;
            int c = (idx & 15) << 2;
            *(float4*)&Bs[r * 64 + c] =
                *(const float4*)&w[(size_t)(kt * 64 + r) * 384 + bn * 64 + c];
        }
        __syncthreads();

        #pragma unroll 16
        for (int k = 0; k < 64; k++) {
            float4 b4 = *(float4*)&Bs[k * 64 + tx * 4];
            float a0 = As[(ty * 4 + 0) * 64 + k];
            float a1 = As[(ty * 4 + 1) * 64 + k];
            float a2 = As[(ty * 4 + 2) * 64 + k];
            float a3 = As[(ty * 4 + 3) * 64 + k];
            acc[0][0] += a0 * b4.x; acc[0][1] += a0 * b4.y; acc[0][2] += a0 * b4.z; acc[0][3] += a0 * b4.w;
            acc[1][0] += a1 * b4.x; acc[1][1] += a1 * b4.y; acc[1][2] += a1 * b4.z; acc[1][3] += a1 * b4.w;
            acc[2][0] += a2 * b4.x; acc[2][1] += a2 * b4.y; acc[2][2] += a2 * b4.z; acc[2][3] += a2 * b4.w;
            acc[3][0] += a3 * b4.x; acc[3][1] += a3 * b4.y; acc[3][2] += a3 * b4.z; acc[3][3] += a3 * b4.w;
        }
        __syncthreads();
    }

    const float scale = 0.17677669529663688f;  // 32^-0.5
    const int row0 = bm * 64 + ty * 4;
    const int col0 = bn * 64 + tx * 4;
    #pragma unroll
    for (int i = 0; i < 4; i++) {
        #pragma unroll
        for (int j = 0; j < 4; j++) {
            int c = col0 + j;
            int r = row0 + i;
            float v = acc[i][j] + bias[c];
            if (c < 128)        g_q[(size_t)r * 128 + c]       = v * scale;
            else if (c < 256)   g_k[(size_t)r * 128 + (c-128)] = v;
            else                g_v[(size_t)r * 128 + (c-256)] = v;
        }
    }
}

// ---------------------------------------------------------------------------
// Neighborhood attention: one warp per (pixel, head), lane = dim element.
// Online softmax over the 7x7 window; K/V loads coalesced 128B per warp.
// ---------------------------------------------------------------------------
__global__ __launch_bounds__(256) void natten_kernel(const float* __restrict__ rpb)
{
    const int gw   = (blockIdx.x * blockDim.x + threadIdx.x) >> 5;
    const int lane = threadIdx.x & 31;
    const int head = gw & 3;
    const int pix  = gw >> 2;
    const int xc   = pix & 63;              // W coordinate
    const int yr   = (pix >> 6) & 63;       // H coordinate
    const int b    = pix >> 12;

    const int sh = min(max(yr - 3, 0), 57); // H - K = 57
    const int sw = min(max(xc - 3, 0), 57);

    const float qd = g_q[(size_t)pix * 128 + head * 32 + lane];
    const int bias_base = head * 169 + (sh - yr + 6) * 13 + (sw - xc + 6);

    float m = -1e30f, l = 0.0f, acc = 0.0f;

    #pragma unroll
    for (int iy = 0; iy < 7; iy++) {
        const int nbase = (((b * 64 + sh + iy) * 64 + sw) * 128) + head * 32 + lane;
        const int brow  = bias_base + iy * 13;
        #pragma unroll
        for (int ix = 0; ix < 7; ix++) {
            float kd = g_k[nbase + ix * 128];
            float s  = qd * kd;
            #pragma unroll
            for (int o = 16; o > 0; o >>= 1)
                s += __shfl_xor_sync(0xffffffffu, s, o);
            s += __ldg(&rpb[brow + ix]);

            float vd   = g_v[nbase + ix * 128];
            float mn   = fmaxf(m, s);
            float corr = __expf(m - mn);
            float p    = __expf(s - mn);
            l   = l * corr + p;
            acc = acc * corr + p * vd;
            m   = mn;
        }
    }
    g_att[(size_t)pix * 128 + head * 32 + lane] = acc / l;
}

// ---------------------------------------------------------------------------
// GEMM 2: out = attn @ w_proj + b_proj.  A: [16384,128], B: [128,128].
// ---------------------------------------------------------------------------
__global__ __launch_bounds__(256) void proj_gemm(
    const float* __restrict__ w,       // [128, 128]
    const float* __restrict__ bias,    // [128]
    float* __restrict__ out)
{
    __shared__ float As[64 * 64];
    __shared__ float Bs[64 * 64];

    const int bm = blockIdx.x;
    const int bn = blockIdx.y;
    const int tid = threadIdx.x;
    const int tx = tid & 15;
    const int ty = tid >> 4;

    float acc[4][4] = {};

    for (int kt = 0; kt < 2; kt++) {
        #pragma unroll
        for (int i = 0; i < 4; i++) {
            int idx = tid + i * 256;
            int r = idx >> 4;
            int c = (idx & 15) << 2;
            *(float4*)&As[r * 64 + c] =
                *(const float4*)&g_att[(size_t)(bm * 64 + r) * 128 + kt * 64 + c];
        }
        #pragma unroll
        for (int i = 0; i < 4; i++) {
            int idx = tid + i * 256;
            int r = idx >> 4;
            int c = (idx & 15) << 2;
            *(float4*)&Bs[r * 64 + c] =
                *(const float4*)&w[(size_t)(kt * 64 + r) * 128 + bn * 64 + c];
        }
        __syncthreads();

        #pragma unroll 16
        for (int k = 0; k < 64; k++) {
            float4 b4 = *(float4*)&Bs[k * 64 + tx * 4];
            float a0 = As[(ty * 4 + 0) * 64 + k];
            float a1 = As[(ty * 4 + 1) * 64 + k];
            float a2 = As[(ty * 4 + 2) * 64 + k];
            float a3 = As[(ty * 4 + 3) * 64 + k];
            acc[0][0] += a0 * b4.x; acc[0][1] += a0 * b4.y; acc[0][2] += a0 * b4.z; acc[0][3] += a0 * b4.w;
            acc[1][0] += a1 * b4.x; acc[1][1] += a1 * b4.y; acc[1][2] += a1 * b4.z; acc[1][3] += a1 * b4.w;
            acc[2][0] += a2 * b4.x; acc[2][1] += a2 * b4.y; acc[2][2] += a2 * b4.z; acc[2][3] += a2 * b4.w;
            acc[3][0] += a3 * b4.x; acc[3][1] += a3 * b4.y; acc[3][2] += a3 * b4.z; acc[3][3] += a3 * b4.w;
        }
        __syncthreads();
    }

    const int row0 = bm * 64 + ty * 4;
    const int col0 = bn * 64 + tx * 4;
    #pragma unroll
    for (int i = 0; i < 4; i++) {
        #pragma unroll
        for (int j = 0; j < 4; j++) {
            int c = col0 + j;
            int r = row0 + i;
            out[(size_t)r * 128 + c] = acc[i][j] + bias[c];
        }
    }
}

// ---------------------------------------------------------------------------
extern "C" void kernel_launch(void* const* d_in, const int* in_sizes, int n_in,
                              void* d_out, int out_size)
{
    const float* x      = (const float*)d_in[0];
    const float* w_qkv  = (const float*)d_in[1];
    const float* b_qkv  = (const float*)d_in[2];
    const float* rpb    = (const float*)d_in[3];
    const float* w_proj = (const float*)d_in[4];
    const float* b_proj = (const float*)d_in[5];
    float* out = (float*)d_out;

    qkv_gemm<<<dim3(256, 6), 256>>>(x, w_qkv, b_qkv);
    natten_kernel<<<8192, 256>>>(rpb);        // 65536 warps = 16384 px * 4 heads
    proj_gemm<<<dim3(256, 2), 256>>>(w_proj, b_proj, out);
}

// round 2
// speedup vs baseline: 1.5586x; 1.5586x over previous
#include <cuda_runtime.h>
#include <math.h>

#define NPIX  16384   // 4*64*64
#define CDIM  128

// Scratch (device globals: no allocations allowed)
__device__ float g_q[NPIX * CDIM];
__device__ float g_k[NPIX * CDIM];
__device__ float g_v[NPIX * CDIM];
__device__ float g_att[NPIX * CDIM];

// ---------------- packed f32x2 helpers (Blackwell FFMA2 path) ----------------
__device__ __forceinline__ unsigned long long pack2(float x, float y) {
    unsigned long long r;
    asm("mov.b64 %0, {%1, %2};" : "=l"(r) : "f"(x), "f"(y));
    return r;
}
__device__ __forceinline__ void fma2(unsigned long long& d,
                                     unsigned long long a,
                                     unsigned long long b) {
    asm("fma.rn.f32x2 %0, %1, %2, %0;" : "+l"(d) : "l"(a), "l"(b));
}
__device__ __forceinline__ float2 unpack2(unsigned long long v) {
    float2 f;
    asm("mov.b64 {%0, %1}, %2;" : "=f"(f.x), "=f"(f.y) : "l"(v));
    return f;
}

// ---------------------------------------------------------------------------
// GEMM 1: qkv = x @ w_qkv + b_qkv ; split into q (scaled), k, v
// 128x128 block tile, BK=32, 8x8 per thread, f32x2 packed FMA.
// Grid (128, 3): bn==0 -> q, bn==1 -> k, bn==2 -> v.
// ---------------------------------------------------------------------------
__global__ __launch_bounds__(256) void qkv_gemm(
    const float* __restrict__ x,       // [16384, 128]
    const float* __restrict__ w,       // [128, 384]
    const float* __restrict__ bias)    // [384]
{
    __shared__ float As[32 * 128];     // transposed: As[k][m]
    __shared__ float Bs[32 * 128];     // Bs[k][n]

    const int bm  = blockIdx.x;
    const int bn  = blockIdx.y;
    const int tid = threadIdx.x;
    const int tx  = tid & 15;          // n
    const int ty  = tid >> 4;          // m

    unsigned long long acc[8][4];
    #pragma unroll
    for (int i = 0; i < 8; i++)
        #pragma unroll
        for (int j = 0; j < 4; j++) acc[i][j] = 0ULL;

    for (int kt = 0; kt < 4; kt++) {
        // A tile: 128 rows x 32 k, load float4 along k, store transposed
        #pragma unroll
        for (int i = 0; i < 4; i++) {
            int f4 = tid + i * 256;          // 0..1023
            int r  = f4 >> 3;                // m 0..127
            int c4 = f4 & 7;                 // k-group 0..7
            float4 v = *(const float4*)&x[(size_t)(bm * 128 + r) * 128 + kt * 32 + c4 * 4];
            As[(c4 * 4 + 0) * 128 + r] = v.x;
            As[(c4 * 4 + 1) * 128 + r] = v.y;
            As[(c4 * 4 + 2) * 128 + r] = v.z;
            As[(c4 * 4 + 3) * 128 + r] = v.w;
        }
        // B tile: 32 k x 128 n
        #pragma unroll
        for (int i = 0; i < 4; i++) {
            int f4  = tid + i * 256;
            int rb  = f4 >> 5;               // k 0..31
            int cb4 = f4 & 31;               // n/4 0..31
            *(float4*)&Bs[rb * 128 + cb4 * 4] =
                *(const float4*)&w[(size_t)(kt * 32 + rb) * 384 + bn * 128 + cb4 * 4];
        }
        __syncthreads();

        #pragma unroll
        for (int kk = 0; kk < 32; kk++) {
            float4 a0 = *(float4*)&As[kk * 128 + ty * 8];
            float4 a1 = *(float4*)&As[kk * 128 + ty * 8 + 4];
            ulonglong2 bA = *(ulonglong2*)&Bs[kk * 128 + tx * 8];
            ulonglong2 bB = *(ulonglong2*)&Bs[kk * 128 + tx * 8 + 4];
            unsigned long long b4[4] = { bA.x, bA.y, bB.x, bB.y };
            unsigned long long ad[8] = {
                pack2(a0.x, a0.x), pack2(a0.y, a0.y), pack2(a0.z, a0.z), pack2(a0.w, a0.w),
                pack2(a1.x, a1.x), pack2(a1.y, a1.y), pack2(a1.z, a1.z), pack2(a1.w, a1.w)
            };
            #pragma unroll
            for (int i = 0; i < 8; i++)
                #pragma unroll
                for (int j = 0; j < 4; j++)
                    fma2(acc[i][j], ad[i], b4[j]);
        }
        __syncthreads();
    }

    const float scale = (bn == 0) ? 0.17677669529663688f : 1.0f;
    float* dst = (bn == 0) ? g_q : (bn == 1) ? g_k : g_v;

    float bloc[8];
    #pragma unroll
    for (int j = 0; j < 8; j++) bloc[j] = bias[bn * 128 + tx * 8 + j];

    #pragma unroll
    for (int i = 0; i < 8; i++) {
        int r = bm * 128 + ty * 8 + i;
        float c[8];
        #pragma unroll
        for (int j = 0; j < 4; j++) {
            float2 f = unpack2(acc[i][j]);
            c[2 * j]     = (f.x + bloc[2 * j])     * scale;
            c[2 * j + 1] = (f.y + bloc[2 * j + 1]) * scale;
        }
        *(float4*)&dst[(size_t)r * 128 + tx * 8]     = make_float4(c[0], c[1], c[2], c[3]);
        *(float4*)&dst[(size_t)r * 128 + tx * 8 + 4] = make_float4(c[4], c[5], c[6], c[7]);
    }
}

// ---------------------------------------------------------------------------
// Neighborhood attention v2: 8x8 pixel tile per block, K/V 14x14 halo in smem
// (padded stride 132 floats -> conflict-free LDS.128). One thread per
// (pixel, head); q and all 49 scores in registers; two-pass softmax.
// ---------------------------------------------------------------------------
#define SM_STRIDE 132                       // floats per (ny,nx) entry
#define SM_FLOATS (14 * 14 * SM_STRIDE)     // 25872

__global__ __launch_bounds__(256) void natten_kernel(const float* __restrict__ rpb)
{
    extern __shared__ float sm[];
    float* Ks = sm;
    float* Vs = sm + SM_FLOATS;

    const int tid  = threadIdx.x;
    const int tile = blockIdx.x & 63;
    const int b    = blockIdx.x >> 6;
    const int Y    = (tile >> 3) * 8;
    const int X    = (tile & 7) * 8;

    const int hb = min(max(Y - 3, 0), 50);
    const int wb = min(max(X - 3, 0), 50);

    // Stage K and V halo: 14x14x128 floats each, coalesced global reads.
    {
        const float4* gk4 = (const float4*)g_k;
        const float4* gv4 = (const float4*)g_v;
        float4* ks4 = (float4*)Ks;
        float4* vs4 = (float4*)Vs;
        #pragma unroll 4
        for (int i = tid; i < 14 * 14 * 32; i += 256) {
            int ny  = i / 448;               // 14*32
            int rem = i - ny * 448;
            int nx  = rem >> 5;
            int c4  = rem & 31;
            int g   = (((b * 64 + hb + ny) * 64) + wb + nx) * 32 + c4;
            int s   = (ny * 14 + nx) * 33 + c4;   // 33 float4 = 132 floats
            ks4[s] = gk4[g];
            vs4[s] = gv4[g];
        }
    }
    __syncthreads();

    const int px   = tid & 63;
    const int head = tid >> 6;
    const int py   = px >> 3;
    const int pxx  = px & 7;
    const int y    = Y + py;
    const int x    = X + pxx;
    const int pixel = (b * 64 + y) * 64 + x;

    const int sh = min(max(y - 3, 0), 57);
    const int sw = min(max(x - 3, 0), 57);
    const int ry = sh - hb;
    const int rx = sw - wb;
    const int bias_base = head * 169 + (sh - y + 6) * 13 + (sw - x + 6);

    // q in registers (8 float4 = 32 dims)
    float4 q[8];
    {
        const float4* gq4 = (const float4*)g_q;
        int base = pixel * 32 + head * 8;
        #pragma unroll
        for (int i = 0; i < 8; i++) q[i] = gq4[base + i];
    }

    // Pass 1: scores
    float s[49];
    #pragma unroll
    for (int iy = 0; iy < 7; iy++) {
        #pragma unroll
        for (int ix = 0; ix < 7; ix++) {
            const float* kp = &Ks[((ry + iy) * 14 + (rx + ix)) * SM_STRIDE + head * 32];
            float d0 = 0.f, d1 = 0.f, d2 = 0.f, d3 = 0.f;
            #pragma unroll
            for (int i = 0; i < 2; i++) {
                float4 k0 = *(const float4*)&kp[i * 16 + 0];
                float4 k1 = *(const float4*)&kp[i * 16 + 4];
                float4 k2 = *(const float4*)&kp[i * 16 + 8];
                float4 k3 = *(const float4*)&kp[i * 16 + 12];
                float4 q0 = q[i * 4 + 0], q1 = q[i * 4 + 1], q2 = q[i * 4 + 2], q3 = q[i * 4 + 3];
                d0 += q0.x * k0.x + q0.y * k0.y + q0.z * k0.z + q0.w * k0.w;
                d1 += q1.x * k1.x + q1.y * k1.y + q1.z * k1.z + q1.w * k1.w;
                d2 += q2.x * k2.x + q2.y * k2.y + q2.z * k2.z + q2.w * k2.w;
                d3 += q3.x * k3.x + q3.y * k3.y + q3.z * k3.z + q3.w * k3.w;
            }
            s[iy * 7 + ix] = (d0 + d1) + (d2 + d3) + __ldg(&rpb[bias_base + iy * 13 + ix]);
        }
    }

    // softmax (two-pass, in registers)
    float m = s[0];
    #pragma unroll
    for (int i = 1; i < 49; i++) m = fmaxf(m, s[i]);
    float l = 0.f;
    #pragma unroll
    for (int i = 0; i < 49; i++) { s[i] = __expf(s[i] - m); l += s[i]; }
    const float inv_l = 1.0f / l;

    // Pass 2: attn @ V
    float4 acc[8];
    #pragma unroll
    for (int i = 0; i < 8; i++) acc[i] = make_float4(0.f, 0.f, 0.f, 0.f);

    #pragma unroll
    for (int iy = 0; iy < 7; iy++) {
        #pragma unroll
        for (int ix = 0; ix < 7; ix++) {
            const float p = s[iy * 7 + ix];
            const float* vp = &Vs[((ry + iy) * 14 + (rx + ix)) * SM_STRIDE + head * 32];
            #pragma unroll
            for (int i = 0; i < 8; i++) {
                float4 v4 = *(const float4*)&vp[i * 4];
                acc[i].x += p * v4.x;
                acc[i].y += p * v4.y;
                acc[i].z += p * v4.z;
                acc[i].w += p * v4.w;
            }
        }
    }

    float4* out4 = (float4*)g_att;
    int obase = pixel * 32 + head * 8;
    #pragma unroll
    for (int i = 0; i < 8; i++) {
        out4[obase + i] = make_float4(acc[i].x * inv_l, acc[i].y * inv_l,
                                      acc[i].z * inv_l, acc[i].w * inv_l);
    }
}

// ---------------------------------------------------------------------------
// GEMM 2: out = attn @ w_proj + b_proj. Same 128x128 f32x2 scheme, grid (128,1).
// ---------------------------------------------------------------------------
__global__ __launch_bounds__(256) void proj_gemm(
    const float* __restrict__ w,       // [128, 128]
    const float* __restrict__ bias,    // [128]
    float* __restrict__ out)
{
    __shared__ float As[32 * 128];
    __shared__ float Bs[32 * 128];

    const int bm  = blockIdx.x;
    const int tid = threadIdx.x;
    const int tx  = tid & 15;
    const int ty  = tid >> 4;

    unsigned long long acc[8][4];
    #pragma unroll
    for (int i = 0; i < 8; i++)
        #pragma unroll
        for (int j = 0; j < 4; j++) acc[i][j] = 0ULL;

    for (int kt = 0; kt < 4; kt++) {
        #pragma unroll
        for (int i = 0; i < 4; i++) {
            int f4 = tid + i * 256;
            int r  = f4 >> 3;
            int c4 = f4 & 7;
            float4 v = *(const float4*)&g_att[(size_t)(bm * 128 + r) * 128 + kt * 32 + c4 * 4];
            As[(c4 * 4 + 0) * 128 + r] = v.x;
            As[(c4 * 4 + 1) * 128 + r] = v.y;
            As[(c4 * 4 + 2) * 128 + r] = v.z;
            As[(c4 * 4 + 3) * 128 + r] = v.w;
        }
        #pragma unroll
        for (int i = 0; i < 4; i++) {
            int f4  = tid + i * 256;
            int rb  = f4 >> 5;
            int cb4 = f4 & 31;
            *(float4*)&Bs[rb * 128 + cb4 * 4] =
                *(const float4*)&w[(size_t)(kt * 32 + rb) * 128 + cb4 * 4];
        }
        __syncthreads();

        #pragma unroll
        for (int kk = 0; kk < 32; kk++) {
            float4 a0 = *(float4*)&As[kk * 128 + ty * 8];
            float4 a1 = *(float4*)&As[kk * 128 + ty * 8 + 4];
            ulonglong2 bA = *(ulonglong2*)&Bs[kk * 128 + tx * 8];
            ulonglong2 bB = *(ulonglong2*)&Bs[kk * 128 + tx * 8 + 4];
            unsigned long long b4[4] = { bA.x, bA.y, bB.x, bB.y };
            unsigned long long ad[8] = {
                pack2(a0.x, a0.x), pack2(a0.y, a0.y), pack2(a0.z, a0.z), pack2(a0.w, a0.w),
                pack2(a1.x, a1.x), pack2(a1.y, a1.y), pack2(a1.z, a1.z), pack2(a1.w, a1.w)
            };
            #pragma unroll
            for (int i = 0; i < 8; i++)
                #pragma unroll
                for (int j = 0; j < 4; j++)
                    fma2(acc[i][j], ad[i], b4[j]);
        }
        __syncthreads();
    }

    float bloc[8];
    #pragma unroll
    for (int j = 0; j < 8; j++) bloc[j] = bias[tx * 8 + j];

    #pragma unroll
    for (int i = 0; i < 8; i++) {
        int r = bm * 128 + ty * 8 + i;
        float c[8];
        #pragma unroll
        for (int j = 0; j < 4; j++) {
            float2 f = unpack2(acc[i][j]);
            c[2 * j]     = f.x + bloc[2 * j];
            c[2 * j + 1] = f.y + bloc[2 * j + 1];
        }
        *(float4*)&out[(size_t)r * 128 + tx * 8]     = make_float4(c[0], c[1], c[2], c[3]);
        *(float4*)&out[(size_t)r * 128 + tx * 8 + 4] = make_float4(c[4], c[5], c[6], c[7]);
    }
}

// ---------------------------------------------------------------------------
extern "C" void kernel_launch(void* const* d_in, const int* in_sizes, int n_in,
                              void* d_out, int out_size)
{
    const float* x      = (const float*)d_in[0];
    const float* w_qkv  = (const float*)d_in[1];
    const float* b_qkv  = (const float*)d_in[2];
    const float* rpb    = (const float*)d_in[3];
    const float* w_proj = (const float*)d_in[4];
    const float* b_proj = (const float*)d_in[5];
    float* out = (float*)d_out;

    static int smem_set = 0;
    if (!smem_set) {
        cudaFuncSetAttribute(natten_kernel,
                             cudaFuncAttributeMaxDynamicSharedMemorySize,
                             2 * SM_FLOATS * (int)sizeof(float));
        smem_set = 1;
    }

    qkv_gemm<<<dim3(128, 3), 256>>>(x, w_qkv, b_qkv);
    natten_kernel<<<256, 256, 2 * SM_FLOATS * sizeof(float)>>>(rpb);
    proj_gemm<<<128, 256>>>(w_proj, b_proj, out);
}

// round 3
// speedup vs baseline: 2.3820x; 1.5283x over previous
#include <cuda_runtime.h>
#include <math.h>
#include <stdint.h>

#define NPIX  16384   // 4*64*64
#define CDIM  128

// Scratch (device globals: no allocations allowed)
__device__ float g_q[NPIX * CDIM];
__device__ float g_k[NPIX * CDIM];
__device__ float g_v[NPIX * CDIM];
__device__ float g_att[NPIX * CDIM];

// ---------------- tf32 helpers ----------------
__device__ __forceinline__ uint32_t f2tf32(float f) {
    uint32_t r;
    asm("cvt.rna.tf32.f32 %0, %1;" : "=r"(r) : "f"(f));
    return r;
}
__device__ __forceinline__ void mma_tf32(float* d, const uint32_t* a,
                                         uint32_t b0, uint32_t b1) {
    asm volatile(
        "mma.sync.aligned.m16n8k8.row.col.f32.tf32.tf32.f32 "
        "{%0,%1,%2,%3}, {%4,%5,%6,%7}, {%8,%9}, {%0,%1,%2,%3};"
        : "+f"(d[0]), "+f"(d[1]), "+f"(d[2]), "+f"(d[3])
        : "r"(a[0]), "r"(a[1]), "r"(a[2]), "r"(a[3]), "r"(b0), "r"(b1));
}

// ---------------------------------------------------------------------------
// TF32 tensor-core GEMM: C[16384, 128*? ] = A[16384,128] @ W[128, LDW] + bias
// CTA tile 128x128, 8 warps (4M x 2N), warp tile 32x64, m16n8k8.
// IS_QKV: blockIdx.y selects q/k/v output (q scaled); else writes outp.
// ---------------------------------------------------------------------------
#define PA 36    // As row stride (floats) -> conflict-free fragment LDS
#define PB 132   // Bs row stride

template<int LDW, bool IS_QKV>
__global__ __launch_bounds__(256) void gemm_tf32(
    const float* __restrict__ A,      // [16384, 128] (ignored for proj)
    const float* __restrict__ W,      // [128, LDW]
    const float* __restrict__ bias,   // [LDW]
    float* __restrict__ outp)         // proj output
{
    __shared__ uint32_t As[128 * PA]; // [m][k]
    __shared__ uint32_t Bs[32 * PB];  // [k][n]

    const int bm   = blockIdx.x;
    const int bn   = blockIdx.y;
    const int tid  = threadIdx.x;
    const int lane = tid & 31;
    const int wrp  = tid >> 5;
    const int g    = lane >> 2;       // group id (row/col within frag)
    const int t    = lane & 3;        // thread in group
    const int wm   = wrp & 3;         // 4 warps along M
    const int wn   = wrp >> 2;        // 2 warps along N

    const float* Aptr = IS_QKV ? A : g_att;

    float acc[2][8][4];
    #pragma unroll
    for (int i = 0; i < 2; i++)
        #pragma unroll
        for (int j = 0; j < 8; j++)
            #pragma unroll
            for (int c = 0; c < 4; c++) acc[i][j][c] = 0.f;

    for (int kt = 0; kt < 4; kt++) {
        // A tile: 128 rows x 32 k, coalesced float4, cvt to tf32
        #pragma unroll
        for (int i = 0; i < 4; i++) {
            int f4 = tid + i * 256;          // 0..1023
            int r  = f4 >> 3;                // 0..127
            int c4 = f4 & 7;                 // 0..7
            float4 v = *(const float4*)&Aptr[(size_t)(bm * 128 + r) * 128 + kt * 32 + c4 * 4];
            As[r * PA + c4 * 4 + 0] = f2tf32(v.x);
            As[r * PA + c4 * 4 + 1] = f2tf32(v.y);
            As[r * PA + c4 * 4 + 2] = f2tf32(v.z);
            As[r * PA + c4 * 4 + 3] = f2tf32(v.w);
        }
        // B tile: 32 k x 128 n
        #pragma unroll
        for (int i = 0; i < 4; i++) {
            int f4  = tid + i * 256;
            int rb  = f4 >> 5;               // k 0..31
            int cb4 = f4 & 31;               // n/4
            float4 v = *(const float4*)&W[(size_t)(kt * 32 + rb) * LDW + bn * 128 + cb4 * 4];
            Bs[rb * PB + cb4 * 4 + 0] = f2tf32(v.x);
            Bs[rb * PB + cb4 * 4 + 1] = f2tf32(v.y);
            Bs[rb * PB + cb4 * 4 + 2] = f2tf32(v.z);
            Bs[rb * PB + cb4 * 4 + 3] = f2tf32(v.w);
        }
        __syncthreads();

        #pragma unroll
        for (int kk = 0; kk < 4; kk++) {
            const int k0 = kk * 8;
            uint32_t a[2][4];
            #pragma unroll
            for (int mi = 0; mi < 2; mi++) {
                int rb = wm * 32 + mi * 16;
                a[mi][0] = As[(rb + g)     * PA + k0 + t];
                a[mi][1] = As[(rb + g + 8) * PA + k0 + t];
                a[mi][2] = As[(rb + g)     * PA + k0 + t + 4];
                a[mi][3] = As[(rb + g + 8) * PA + k0 + t + 4];
            }
            #pragma unroll
            for (int ni = 0; ni < 8; ni++) {
                int cb = wn * 64 + ni * 8;
                uint32_t b0 = Bs[(k0 + t)     * PB + cb + g];
                uint32_t b1 = Bs[(k0 + t + 4) * PB + cb + g];
                mma_tf32(acc[0][ni], a[0], b0, b1);
                mma_tf32(acc[1][ni], a[1], b0, b1);
            }
        }
        __syncthreads();
    }

    // Epilogue
    const float scale = (IS_QKV && bn == 0) ? 0.17677669529663688f : 1.0f;
    float* dst;
    if (IS_QKV) dst = (bn == 0) ? g_q : (bn == 1) ? g_k : g_v;
    else        dst = outp;

    #pragma unroll
    for (int ni = 0; ni < 8; ni++) {
        int c  = wn * 64 + ni * 8 + t * 2;
        float b0 = bias[(IS_QKV ? bn * 128 : 0) + c];
        float b1 = bias[(IS_QKV ? bn * 128 : 0) + c + 1];
        #pragma unroll
        for (int mi = 0; mi < 2; mi++) {
            int r0 = bm * 128 + wm * 32 + mi * 16 + g;
            float2 v0 = make_float2((acc[mi][ni][0] + b0) * scale,
                                    (acc[mi][ni][1] + b1) * scale);
            float2 v1 = make_float2((acc[mi][ni][2] + b0) * scale,
                                    (acc[mi][ni][3] + b1) * scale);
            *(float2*)&dst[(size_t)r0 * 128 + c]       = v0;
            *(float2*)&dst[(size_t)(r0 + 8) * 128 + c] = v1;
        }
    }
}

// ---------------------------------------------------------------------------
// Neighborhood attention: 8x8 pixel tile per block, K/V 14x14 halo in smem
// (padded stride 132 floats -> conflict-free LDS.128). One thread per
// (pixel, head); q and all 49 scores in registers; two-pass softmax.
// ---------------------------------------------------------------------------
#define SM_STRIDE 132                       // floats per (ny,nx) entry
#define SM_FLOATS (14 * 14 * SM_STRIDE)     // 25872

__global__ __launch_bounds__(256) void natten_kernel(const float* __restrict__ rpb)
{
    extern __shared__ float sm[];
    float* Ks = sm;
    float* Vs = sm + SM_FLOATS;

    const int tid  = threadIdx.x;
    const int tile = blockIdx.x & 63;
    const int b    = blockIdx.x >> 6;
    const int Y    = (tile >> 3) * 8;
    const int X    = (tile & 7) * 8;

    const int hb = min(max(Y - 3, 0), 50);
    const int wb = min(max(X - 3, 0), 50);

    {
        const float4* gk4 = (const float4*)g_k;
        const float4* gv4 = (const float4*)g_v;
        float4* ks4 = (float4*)Ks;
        float4* vs4 = (float4*)Vs;
        #pragma unroll 4
        for (int i = tid; i < 14 * 14 * 32; i += 256) {
            int ny  = i / 448;
            int rem = i - ny * 448;
            int nx  = rem >> 5;
            int c4  = rem & 31;
            int gg  = (((b * 64 + hb + ny) * 64) + wb + nx) * 32 + c4;
            int s   = (ny * 14 + nx) * 33 + c4;
            ks4[s] = gk4[gg];
            vs4[s] = gv4[gg];
        }
    }
    __syncthreads();

    const int px   = tid & 63;
    const int head = tid >> 6;
    const int py   = px >> 3;
    const int pxx  = px & 7;
    const int y    = Y + py;
    const int x    = X + pxx;
    const int pixel = (b * 64 + y) * 64 + x;

    const int sh = min(max(y - 3, 0), 57);
    const int sw = min(max(x - 3, 0), 57);
    const int ry = sh - hb;
    const int rx = sw - wb;
    const int bias_base = head * 169 + (sh - y + 6) * 13 + (sw - x + 6);

    float4 q[8];
    {
        const float4* gq4 = (const float4*)g_q;
        int base = pixel * 32 + head * 8;
        #pragma unroll
        for (int i = 0; i < 8; i++) q[i] = gq4[base + i];
    }

    float s[49];
    #pragma unroll
    for (int iy = 0; iy < 7; iy++) {
        #pragma unroll
        for (int ix = 0; ix < 7; ix++) {
            const float* kp = &Ks[((ry + iy) * 14 + (rx + ix)) * SM_STRIDE + head * 32];
            float d0 = 0.f, d1 = 0.f, d2 = 0.f, d3 = 0.f;
            #pragma unroll
            for (int i = 0; i < 2; i++) {
                float4 k0 = *(const float4*)&kp[i * 16 + 0];
                float4 k1 = *(const float4*)&kp[i * 16 + 4];
                float4 k2 = *(const float4*)&kp[i * 16 + 8];
                float4 k3 = *(const float4*)&kp[i * 16 + 12];
                float4 q0 = q[i * 4 + 0], q1 = q[i * 4 + 1], q2 = q[i * 4 + 2], q3 = q[i * 4 + 3];
                d0 += q0.x * k0.x + q0.y * k0.y + q0.z * k0.z + q0.w * k0.w;
                d1 += q1.x * k1.x + q1.y * k1.y + q1.z * k1.z + q1.w * k1.w;
                d2 += q2.x * k2.x + q2.y * k2.y + q2.z * k2.z + q2.w * k2.w;
                d3 += q3.x * k3.x + q3.y * k3.y + q3.z * k3.z + q3.w * k3.w;
            }
            s[iy * 7 + ix] = (d0 + d1) + (d2 + d3) + __ldg(&rpb[bias_base + iy * 13 + ix]);
        }
    }

    float m = s[0];
    #pragma unroll
    for (int i = 1; i < 49; i++) m = fmaxf(m, s[i]);
    float l = 0.f;
    #pragma unroll
    for (int i = 0; i < 49; i++) { s[i] = __expf(s[i] - m); l += s[i]; }
    const float inv_l = 1.0f / l;

    float4 acc[8];
    #pragma unroll
    for (int i = 0; i < 8; i++) acc[i] = make_float4(0.f, 0.f, 0.f, 0.f);

    #pragma unroll
    for (int iy = 0; iy < 7; iy++) {
        #pragma unroll
        for (int ix = 0; ix < 7; ix++) {
            const float p = s[iy * 7 + ix];
            const float* vp = &Vs[((ry + iy) * 14 + (rx + ix)) * SM_STRIDE + head * 32];
            #pragma unroll
            for (int i = 0; i < 8; i++) {
                float4 v4 = *(const float4*)&vp[i * 4];
                acc[i].x += p * v4.x;
                acc[i].y += p * v4.y;
                acc[i].z += p * v4.z;
                acc[i].w += p * v4.w;
            }
        }
    }

    float4* out4 = (float4*)g_att;
    int obase = pixel * 32 + head * 8;
    #pragma unroll
    for (int i = 0; i < 8; i++) {
        out4[obase + i] = make_float4(acc[i].x * inv_l, acc[i].y * inv_l,
                                      acc[i].z * inv_l, acc[i].w * inv_l);
    }
}

// ---------------------------------------------------------------------------
extern "C" void kernel_launch(void* const* d_in, const int* in_sizes, int n_in,
                              void* d_out, int out_size)
{
    const float* x      = (const float*)d_in[0];
    const float* w_qkv  = (const float*)d_in[1];
    const float* b_qkv  = (const float*)d_in[2];
    const float* rpb    = (const float*)d_in[3];
    const float* w_proj = (const float*)d_in[4];
    const float* b_proj = (const float*)d_in[5];
    float* out = (float*)d_out;

    cudaFuncSetAttribute(natten_kernel,
                         cudaFuncAttributeMaxDynamicSharedMemorySize,
                         2 * SM_FLOATS * (int)sizeof(float));

    gemm_tf32<384, true><<<dim3(128, 3), 256>>>(x, w_qkv, b_qkv, nullptr);
    natten_kernel<<<256, 256, 2 * SM_FLOATS * sizeof(float)>>>(rpb);
    gemm_tf32<128, false><<<dim3(128, 1), 256>>>(nullptr, w_proj, b_proj, out);
}

// round 4
// speedup vs baseline: 2.4933x; 1.0467x over previous
#include <cuda_runtime.h>
#include <math.h>
#include <stdint.h>

#define NPIX  16384   // 4*64*64
#define CDIM  128

// Scratch (device globals: no allocations allowed)
__device__ float g_q[NPIX * CDIM];
__device__ float g_k[NPIX * CDIM];
__device__ float g_v[NPIX * CDIM];
__device__ float g_att[NPIX * CDIM];

// ---------------- tf32 helpers ----------------
__device__ __forceinline__ uint32_t f2tf32(float f) {
    uint32_t r;
    asm("cvt.rna.tf32.f32 %0, %1;" : "=r"(r) : "f"(f));
    return r;
}
__device__ __forceinline__ void mma_tf32(float* d, const uint32_t* a,
                                         uint32_t b0, uint32_t b1) {
    asm volatile(
        "mma.sync.aligned.m16n8k8.row.col.f32.tf32.tf32.f32 "
        "{%0,%1,%2,%3}, {%4,%5,%6,%7}, {%8,%9}, {%0,%1,%2,%3};"
        : "+f"(d[0]), "+f"(d[1]), "+f"(d[2]), "+f"(d[3])
        : "r"(a[0]), "r"(a[1]), "r"(a[2]), "r"(a[3]), "r"(b0), "r"(b1));
}

// ---------------------------------------------------------------------------
// TF32 tensor-core GEMM v2: BM=64 CTA tile, persistent B (128x128 in smem),
// double-buffered A chunks (BK=32). 8 warps: 2 over M (32 rows each),
// 4 over N (32 cols each). One __syncthreads per k-chunk.
// ---------------------------------------------------------------------------
#define PA 36    // As row stride (u32) -> conflict-free fragment LDS
#define PB 132   // Bs row stride
#define GEMM_SMEM ((128 * PB + 2 * 64 * PA) * 4)   // 86016 B

template<int LDW, bool IS_QKV>
__global__ __launch_bounds__(256) void gemm_tf32(
    const float* __restrict__ A,      // [16384, 128] (ignored for proj)
    const float* __restrict__ W,      // [128, LDW]
    const float* __restrict__ bias,   // [LDW]
    float* __restrict__ outp)         // proj output
{
    extern __shared__ uint32_t smem_g[];
    uint32_t* Bs = smem_g;                    // [128][PB]
    uint32_t* As = smem_g + 128 * PB;         // 2 x [64][PA]

    const int bm   = blockIdx.x;
    const int bn   = blockIdx.y;
    const int tid  = threadIdx.x;
    const int lane = tid & 31;
    const int wrp  = tid >> 5;
    const int g    = lane >> 2;
    const int t    = lane & 3;
    const int wm   = wrp & 1;        // 2 warps along M (32 rows each)
    const int wn   = wrp >> 1;       // 4 warps along N (32 cols each)

    const float* Aptr = IS_QKV ? A : g_att;

    // A-chunk staging coords (2 float4 per thread per 64x32 chunk)
    const int ar0 = (tid + 0)   >> 3;         // row 0..63
    const int ac0 = (tid & 7);                // k-group
    const int ar1 = (tid + 256) >> 3;
    const int ac1 = (tid + 256) & 7;

    float4 areg0, areg1;
    // Prefetch A chunk 0
    areg0 = *(const float4*)&Aptr[(size_t)(bm * 64 + ar0) * 128 + ac0 * 4];
    areg1 = *(const float4*)&Aptr[(size_t)(bm * 64 + ar1) * 128 + ac1 * 4];

    // Load full B tile: 128k x 128n (16 float4 per thread)
    #pragma unroll
    for (int i = 0; i < 16; i++) {
        int f4  = tid + i * 256;
        int rb  = f4 >> 5;
        int cb4 = f4 & 31;
        float4 v = *(const float4*)&W[(size_t)rb * LDW + bn * 128 + cb4 * 4];
        Bs[rb * PB + cb4 * 4 + 0] = f2tf32(v.x);
        Bs[rb * PB + cb4 * 4 + 1] = f2tf32(v.y);
        Bs[rb * PB + cb4 * 4 + 2] = f2tf32(v.z);
        Bs[rb * PB + cb4 * 4 + 3] = f2tf32(v.w);
    }
    // Store A chunk 0 into buf 0
    {
        uint32_t* buf = As;
        buf[ar0 * PA + ac0 * 4 + 0] = f2tf32(areg0.x);
        buf[ar0 * PA + ac0 * 4 + 1] = f2tf32(areg0.y);
        buf[ar0 * PA + ac0 * 4 + 2] = f2tf32(areg0.z);
        buf[ar0 * PA + ac0 * 4 + 3] = f2tf32(areg0.w);
        buf[ar1 * PA + ac1 * 4 + 0] = f2tf32(areg1.x);
        buf[ar1 * PA + ac1 * 4 + 1] = f2tf32(areg1.y);
        buf[ar1 * PA + ac1 * 4 + 2] = f2tf32(areg1.z);
        buf[ar1 * PA + ac1 * 4 + 3] = f2tf32(areg1.w);
    }
    __syncthreads();

    float acc[2][4][4];
    #pragma unroll
    for (int i = 0; i < 2; i++)
        #pragma unroll
        for (int j = 0; j < 4; j++)
            #pragma unroll
            for (int c = 0; c < 4; c++) acc[i][j][c] = 0.f;

    #pragma unroll
    for (int kt = 0; kt < 4; kt++) {
        // Prefetch next A chunk while mma runs
        if (kt < 3) {
            areg0 = *(const float4*)&Aptr[(size_t)(bm * 64 + ar0) * 128 + (kt + 1) * 32 + ac0 * 4];
            areg1 = *(const float4*)&Aptr[(size_t)(bm * 64 + ar1) * 128 + (kt + 1) * 32 + ac1 * 4];
        }

        const uint32_t* abuf = As + (kt & 1) * 64 * PA;
        #pragma unroll
        for (int kk = 0; kk < 4; kk++) {
            const int k0 = kk * 8;
            const int kr = kt * 32 + k0;
            uint32_t a[2][4];
            #pragma unroll
            for (int mi = 0; mi < 2; mi++) {
                int rb = wm * 32 + mi * 16;
                a[mi][0] = abuf[(rb + g)     * PA + k0 + t];
                a[mi][1] = abuf[(rb + g + 8) * PA + k0 + t];
                a[mi][2] = abuf[(rb + g)     * PA + k0 + t + 4];
                a[mi][3] = abuf[(rb + g + 8) * PA + k0 + t + 4];
            }
            #pragma unroll
            for (int ni = 0; ni < 4; ni++) {
                int cb = wn * 32 + ni * 8;
                uint32_t b0 = Bs[(kr + t)     * PB + cb + g];
                uint32_t b1 = Bs[(kr + t + 4) * PB + cb + g];
                mma_tf32(acc[0][ni], a[0], b0, b1);
                mma_tf32(acc[1][ni], a[1], b0, b1);
            }
        }

        if (kt < 3) {
            // buf (kt+1)&1 was last read in iteration kt-1; sync at end of
            // kt-1 guarantees it's free. Write next chunk, then sync.
            uint32_t* buf = As + ((kt + 1) & 1) * 64 * PA;
            buf[ar0 * PA + ac0 * 4 + 0] = f2tf32(areg0.x);
            buf[ar0 * PA + ac0 * 4 + 1] = f2tf32(areg0.y);
            buf[ar0 * PA + ac0 * 4 + 2] = f2tf32(areg0.z);
            buf[ar0 * PA + ac0 * 4 + 3] = f2tf32(areg0.w);
            buf[ar1 * PA + ac1 * 4 + 0] = f2tf32(areg1.x);
            buf[ar1 * PA + ac1 * 4 + 1] = f2tf32(areg1.y);
            buf[ar1 * PA + ac1 * 4 + 2] = f2tf32(areg1.z);
            buf[ar1 * PA + ac1 * 4 + 3] = f2tf32(areg1.w);
            __syncthreads();
        }
    }

    // Epilogue
    const float scale = (IS_QKV && bn == 0) ? 0.17677669529663688f : 1.0f;
    float* dst;
    if (IS_QKV) dst = (bn == 0) ? g_q : (bn == 1) ? g_k : g_v;
    else        dst = outp;

    #pragma unroll
    for (int ni = 0; ni < 4; ni++) {
        int c  = wn * 32 + ni * 8 + t * 2;
        float b0 = bias[(IS_QKV ? bn * 128 : 0) + c];
        float b1 = bias[(IS_QKV ? bn * 128 : 0) + c + 1];
        #pragma unroll
        for (int mi = 0; mi < 2; mi++) {
            int r0 = bm * 64 + wm * 32 + mi * 16 + g;
            float2 v0 = make_float2((acc[mi][ni][0] + b0) * scale,
                                    (acc[mi][ni][1] + b1) * scale);
            float2 v1 = make_float2((acc[mi][ni][2] + b0) * scale,
                                    (acc[mi][ni][3] + b1) * scale);
            *(float2*)&dst[(size_t)r0 * 128 + c]       = v0;
            *(float2*)&dst[(size_t)(r0 + 8) * 128 + c] = v1;
        }
    }
}

// ---------------------------------------------------------------------------
// Neighborhood attention v3: 8x8 pixel tile, ONE 14x14 halo buffer reused
// (K for score pass, then restaged with V for AV pass) -> 103.5KB smem,
// 2 CTAs/SM, all 256 blocks in a single wave.
// ---------------------------------------------------------------------------
#define SM_STRIDE 132                       // floats per (ny,nx) entry
#define SM_FLOATS (14 * 14 * SM_STRIDE)     // 25872 floats = 103488 B

__global__ __launch_bounds__(256, 2) void natten_kernel(const float* __restrict__ rpb)
{
    extern __shared__ float sm[];
    float* KVs = sm;

    const int tid  = threadIdx.x;
    const int tile = blockIdx.x & 63;
    const int b    = blockIdx.x >> 6;
    const int Y    = (tile >> 3) * 8;
    const int X    = (tile & 7) * 8;

    const int hb = min(max(Y - 3, 0), 50);
    const int wb = min(max(X - 3, 0), 50);

    // Stage K halo
    {
        const float4* gk4 = (const float4*)g_k;
        float4* s4 = (float4*)KVs;
        for (int i = tid; i < 14 * 14 * 32; i += 256) {
            int ny  = i / 448;
            int rem = i - ny * 448;
            int nx  = rem >> 5;
            int c4  = rem & 31;
            s4[(ny * 14 + nx) * 33 + c4] =
                gk4[(((b * 64 + hb + ny) * 64) + wb + nx) * 32 + c4];
        }
    }

    const int px   = tid & 63;
    const int head = tid >> 6;
    const int py   = px >> 3;
    const int pxx  = px & 7;
    const int y    = Y + py;
    const int x    = X + pxx;
    const int pixel = (b * 64 + y) * 64 + x;

    const int sh = min(max(y - 3, 0), 57);
    const int sw = min(max(x - 3, 0), 57);
    const int ry = sh - hb;
    const int rx = sw - wb;
    const int bias_base = head * 169 + (sh - y + 6) * 13 + (sw - x + 6);

    // q in registers (8 float4 = 32 dims) — overlaps with K staging
    float4 q[8];
    {
        const float4* gq4 = (const float4*)g_q;
        int base = pixel * 32 + head * 8;
        #pragma unroll
        for (int i = 0; i < 8; i++) q[i] = gq4[base + i];
    }
    __syncthreads();

    // Pass 1: scores
    float s[49];
    #pragma unroll
    for (int iy = 0; iy < 7; iy++) {
        #pragma unroll
        for (int ix = 0; ix < 7; ix++) {
            const float* kp = &KVs[((ry + iy) * 14 + (rx + ix)) * SM_STRIDE + head * 32];
            float d0 = 0.f, d1 = 0.f, d2 = 0.f, d3 = 0.f;
            #pragma unroll
            for (int i = 0; i < 2; i++) {
                float4 k0 = *(const float4*)&kp[i * 16 + 0];
                float4 k1 = *(const float4*)&kp[i * 16 + 4];
                float4 k2 = *(const float4*)&kp[i * 16 + 8];
                float4 k3 = *(const float4*)&kp[i * 16 + 12];
                float4 q0 = q[i * 4 + 0], q1 = q[i * 4 + 1], q2 = q[i * 4 + 2], q3 = q[i * 4 + 3];
                d0 += q0.x * k0.x + q0.y * k0.y + q0.z * k0.z + q0.w * k0.w;
                d1 += q1.x * k1.x + q1.y * k1.y + q1.z * k1.z + q1.w * k1.w;
                d2 += q2.x * k2.x + q2.y * k2.y + q2.z * k2.z + q2.w * k2.w;
                d3 += q3.x * k3.x + q3.y * k3.y + q3.z * k3.z + q3.w * k3.w;
            }
            s[iy * 7 + ix] = (d0 + d1) + (d2 + d3) + __ldg(&rpb[bias_base + iy * 13 + ix]);
        }
    }
    __syncthreads();   // everyone done reading K

    // Restage with V halo
    {
        const float4* gv4 = (const float4*)g_v;
        float4* s4 = (float4*)KVs;
        for (int i = tid; i < 14 * 14 * 32; i += 256) {
            int ny  = i / 448;
            int rem = i - ny * 448;
            int nx  = rem >> 5;
            int c4  = rem & 31;
            s4[(ny * 14 + nx) * 33 + c4] =
                gv4[(((b * 64 + hb + ny) * 64) + wb + nx) * 32 + c4];
        }
    }

    // softmax in registers (overlaps with V staging)
    float m = s[0];
    #pragma unroll
    for (int i = 1; i < 49; i++) m = fmaxf(m, s[i]);
    float l = 0.f;
    #pragma unroll
    for (int i = 0; i < 49; i++) { s[i] = __expf(s[i] - m); l += s[i]; }
    const float inv_l = 1.0f / l;
    __syncthreads();

    // Pass 2: attn @ V
    float4 acc[8];
    #pragma unroll
    for (int i = 0; i < 8; i++) acc[i] = make_float4(0.f, 0.f, 0.f, 0.f);

    #pragma unroll
    for (int iy = 0; iy < 7; iy++) {
        #pragma unroll
        for (int ix = 0; ix < 7; ix++) {
            const float p = s[iy * 7 + ix];
            const float* vp = &KVs[((ry + iy) * 14 + (rx + ix)) * SM_STRIDE + head * 32];
            #pragma unroll
            for (int i = 0; i < 8; i++) {
                float4 v4 = *(const float4*)&vp[i * 4];
                acc[i].x += p * v4.x;
                acc[i].y += p * v4.y;
                acc[i].z += p * v4.z;
                acc[i].w += p * v4.w;
            }
        }
    }

    float4* out4 = (float4*)g_att;
    int obase = pixel * 32 + head * 8;
    #pragma unroll
    for (int i = 0; i < 8; i++) {
        out4[obase + i] = make_float4(acc[i].x * inv_l, acc[i].y * inv_l,
                                      acc[i].z * inv_l, acc[i].w * inv_l);
    }
}

// ---------------------------------------------------------------------------
extern "C" void kernel_launch(void* const* d_in, const int* in_sizes, int n_in,
                              void* d_out, int out_size)
{
    const float* x      = (const float*)d_in[0];
    const float* w_qkv  = (const float*)d_in[1];
    const float* b_qkv  = (const float*)d_in[2];
    const float* rpb    = (const float*)d_in[3];
    const float* w_proj = (const float*)d_in[4];
    const float* b_proj = (const float*)d_in[5];
    float* out = (float*)d_out;

    cudaFuncSetAttribute(natten_kernel,
                         cudaFuncAttributeMaxDynamicSharedMemorySize,
                         SM_FLOATS * (int)sizeof(float));
    cudaFuncSetAttribute((const void*)gemm_tf32<384, true>,
                         cudaFuncAttributeMaxDynamicSharedMemorySize, GEMM_SMEM);
    cudaFuncSetAttribute((const void*)gemm_tf32<128, false>,
                         cudaFuncAttributeMaxDynamicSharedMemorySize, GEMM_SMEM);

    gemm_tf32<384, true><<<dim3(256, 3), 256, GEMM_SMEM>>>(x, w_qkv, b_qkv, nullptr);
    natten_kernel<<<256, 256, SM_FLOATS * sizeof(float)>>>(rpb);
    gemm_tf32<128, false><<<dim3(256, 1), 256, GEMM_SMEM>>>(nullptr, w_proj, b_proj, out);
}